// round 4
// baseline (speedup 1.0000x reference)
#include <cuda_runtime.h>
#include <math.h>

#define NN 6144
#define CC 128
#define KH 2
#define MAXD 192          // binomial(6143,0.01): mean deg 61, max row deg ~<110

// ---------------- scratch (__device__ globals; no allocation) ----------------
__device__ float g_xnorm[NN * CC];
__device__ float g_h[KH * NN * CC];
__device__ float g_ssrc[KH * NN];
__device__ float g_sdst[KH * NN];
__device__ float g_attln[KH * NN * CC];
__device__ int   g_cols[NN * MAXD];
__device__ int   g_deg[NN];

// ---------------- reductions (128-thread blocks) ----------------
__device__ __forceinline__ float warpSum(float v) {
#pragma unroll
    for (int o = 16; o > 0; o >>= 1) v += __shfl_xor_sync(0xffffffffu, v, o);
    return v;
}
__device__ __forceinline__ float warpMax(float v) {
#pragma unroll
    for (int o = 16; o > 0; o >>= 1) v = fmaxf(v, __shfl_xor_sync(0xffffffffu, v, o));
    return v;
}
__device__ __forceinline__ float blockSum128(float v, float* red) {
    v = warpSum(v);
    if ((threadIdx.x & 31) == 0) red[threadIdx.x >> 5] = v;
    __syncthreads();
    float r = red[0] + red[1] + red[2] + red[3];
    __syncthreads();
    return r;
}
__device__ __forceinline__ float blockMax128(float v, float* red) {
    v = warpMax(v);
    if ((threadIdx.x & 31) == 0) red[threadIdx.x >> 5] = v;
    __syncthreads();
    float r = fmaxf(fmaxf(red[0], red[1]), fmaxf(red[2], red[3]));
    __syncthreads();
    return r;
}

// ---------------- kernel 1: ELL build from adj (warp per row) ----------------
__global__ __launch_bounds__(256) void k_csr(const float* __restrict__ adj) {
    int gw = (blockIdx.x * blockDim.x + threadIdx.x) >> 5;
    int lane = threadIdx.x & 31;
    if (gw >= NN) return;
    int row = gw;
    const float4* a4 = (const float4*)(adj + (size_t)row * NN);
    int* rcols = g_cols + (size_t)row * MAXD;
    int cnt = 0;
#pragma unroll 1
    for (int it = 0; it < NN / 128; it++) {
        int base = it * 128 + lane * 4;
        float4 v = a4[it * 32 + lane];
        unsigned m = 0;
        if (v.x > 0.f || base + 0 == row) m |= 1u;
        if (v.y > 0.f || base + 1 == row) m |= 2u;
        if (v.z > 0.f || base + 2 == row) m |= 4u;
        if (v.w > 0.f || base + 3 == row) m |= 8u;
        int c = __popc(m);
        int incl = c;
#pragma unroll
        for (int o = 1; o < 32; o <<= 1) {
            int t = __shfl_up_sync(0xffffffffu, incl, o);
            if (lane >= o) incl += t;
        }
        int total = __shfl_sync(0xffffffffu, incl, 31);
        int off = cnt + incl - c;      // exclusive offset for this thread
        if (m & 1u) { if (off < MAXD) rcols[off] = base + 0; off++; }
        if (m & 2u) { if (off < MAXD) rcols[off] = base + 1; off++; }
        if (m & 4u) { if (off < MAXD) rcols[off] = base + 2; off++; }
        if (m & 8u) { if (off < MAXD) rcols[off] = base + 3; off++; }
        cnt += total;
    }
    if (lane == 0) g_deg[row] = cnt < MAXD ? cnt : MAXD;
}

// ---------------- kernel 2: LayerNorm(x) ----------------
__global__ __launch_bounds__(128) void k_ln(const float* __restrict__ x,
                                            const float* __restrict__ g,
                                            const float* __restrict__ b) {
    __shared__ float red[4];
    int r = blockIdx.x, t = threadIdx.x;
    float v = x[r * CC + t];
    float mean = blockSum128(v, red) * (1.0f / CC);
    float dv = v - mean;
    float var = blockSum128(dv * dv, red) * (1.0f / CC);
    g_xnorm[r * CC + t] = dv * rsqrtf(var + 1e-5f) * g[t] + b[t];
}

// ---------------- tiled GEMM helper: 64-row tile, out = in @ W^T ------------
// Static smem (<48 KB): K chunked by 32. sIn[64][33], sW[32][129] (sW[k][o]).
// 256 threads -> ty in [0,16) rows*4, tx in [0,16) outs*8.
#define KCH 32

struct GemmSmem {
    float sIn[64][KCH + 1];
    float sW[KCH][CC + 1];
};

__device__ __forceinline__ void gemm_chunk(const float* __restrict__ in, int rowBase,
                                           const float* __restrict__ W, int kBase,
                                           GemmSmem& sm, int tid, int ty, int tx,
                                           float acc[4][8]) {
    // load input chunk: 64 rows x 32 k = 2048 elems
#pragma unroll
    for (int i = tid; i < 64 * KCH; i += 256) {
        int rr = i >> 5, kk = i & 31;
        sm.sIn[rr][kk] = in[(size_t)(rowBase + rr) * CC + kBase + kk];
    }
    // load W chunk transposed: sW[k][o] = W[o*CC + kBase + k], 128 o x 32 k
#pragma unroll
    for (int i = tid; i < CC * KCH; i += 256) {
        int o = i >> 5, kk = i & 31;
        sm.sW[kk][o] = W[(size_t)o * CC + kBase + kk];
    }
    __syncthreads();
#pragma unroll 8
    for (int k = 0; k < KCH; k++) {
        float a0 = sm.sIn[ty * 4 + 0][k];
        float a1 = sm.sIn[ty * 4 + 1][k];
        float a2 = sm.sIn[ty * 4 + 2][k];
        float a3 = sm.sIn[ty * 4 + 3][k];
        float bb[8];
#pragma unroll
        for (int q = 0; q < 8; q++) bb[q] = sm.sW[k][tx * 8 + q];
#pragma unroll
        for (int q = 0; q < 8; q++) {
            acc[0][q] = fmaf(a0, bb[q], acc[0][q]);
            acc[1][q] = fmaf(a1, bb[q], acc[1][q]);
            acc[2][q] = fmaf(a2, bb[q], acc[2][q]);
            acc[3][q] = fmaf(a3, bb[q], acc[3][q]);
        }
    }
    __syncthreads();
}

// h[head] = x_norm @ ff0_w[head]^T       grid: (NN/64, KH)
__global__ __launch_bounds__(256) void k_gemm_h(const float* __restrict__ ff0_w) {
    __shared__ GemmSmem sm;
    int tid = threadIdx.x;
    int head = blockIdx.y;
    int rowBase = blockIdx.x * 64;
    int ty = tid >> 4, tx = tid & 15;
    const float* W = ff0_w + head * CC * CC;
    float acc[4][8] = {};
#pragma unroll 1
    for (int kBase = 0; kBase < CC; kBase += KCH)
        gemm_chunk(g_xnorm, rowBase, W, kBase, sm, tid, ty, tx, acc);
    float* out = g_h + (size_t)head * NN * CC;
#pragma unroll
    for (int i = 0; i < 4; i++) {
        float4* p = (float4*)(out + (size_t)(rowBase + ty * 4 + i) * CC + tx * 8);
        p[0] = make_float4(acc[i][0], acc[i][1], acc[i][2], acc[i][3]);
        p[1] = make_float4(acc[i][4], acc[i][5], acc[i][6], acc[i][7]);
    }
}

// ---------------- kernel 4: attention scores per node ----------------
__global__ __launch_bounds__(128) void k_scores(const float* __restrict__ attn_w) { // grid (NN, KH)
    __shared__ float red[4];
    int r = blockIdx.x, head = blockIdx.y, t = threadIdx.x;
    float hv = g_h[(size_t)head * NN * CC + r * CC + t];
    float s1 = blockSum128(hv * attn_w[head * 2 * CC + t], red);
    float s2 = blockSum128(hv * attn_w[head * 2 * CC + CC + t], red);
    if (t == 0) {
        g_ssrc[head * NN + r] = s1;
        g_sdst[head * NN + r] = s2;
    }
}

// ---------------- kernel 5: sparse softmax + PV + residual + LN ----------------
__global__ __launch_bounds__(128) void k_attn(const float* __restrict__ x,
                                              const float* __restrict__ g2,
                                              const float* __restrict__ b2) { // grid (NN, KH)
    __shared__ float ev[MAXD];
    __shared__ int cl[MAXD];
    __shared__ float red[4];
    int r = blockIdx.x, head = blockIdx.y, tid = threadIdx.x;
    int d = g_deg[r];
    float srow = g_ssrc[head * NN + r];
    const int* rcols = g_cols + (size_t)r * MAXD;

    float lmax = -1e30f;
    for (int j = tid; j < d; j += 128) {
        int c = rcols[j];
        float e = srow + g_sdst[head * NN + c];
        e = e > 0.f ? e : 0.01f * e;      // leaky_relu, slope 0.01
        ev[j] = e;
        cl[j] = c;
        lmax = fmaxf(lmax, e);
    }
    float m = blockMax128(lmax, red);
    float lsum = 0.f;
    for (int j = tid; j < d; j += 128) {
        float p = expf(ev[j] - m);
        ev[j] = p;
        lsum += p;
    }
    float Z = blockSum128(lsum, red);     // syncs inside make ev/cl visible

    const float* hh = g_h + (size_t)head * NN * CC;
    float acc = 0.f;
    int j = 0;
    for (; j + 4 <= d; j += 4) {          // MLP=4 on the L2-resident h gathers
        float p0 = ev[j + 0], p1 = ev[j + 1], p2 = ev[j + 2], p3 = ev[j + 3];
        const float* r0 = hh + (size_t)cl[j + 0] * CC;
        const float* r1 = hh + (size_t)cl[j + 1] * CC;
        const float* r2 = hh + (size_t)cl[j + 2] * CC;
        const float* r3 = hh + (size_t)cl[j + 3] * CC;
        float v0 = r0[tid], v1 = r1[tid], v2 = r2[tid], v3 = r3[tid];
        acc = fmaf(p0, v0, acc);
        acc = fmaf(p1, v1, acc);
        acc = fmaf(p2, v2, acc);
        acc = fmaf(p3, v3, acc);
    }
    for (; j < d; j++) acc = fmaf(ev[j], hh[(size_t)cl[j] * CC + tid], acc);

    float att = acc / Z + x[r * CC + tid];     // residual with pre-norm x
    float mean = blockSum128(att, red) * (1.0f / CC);
    float dv = att - mean;
    float var = blockSum128(dv * dv, red) * (1.0f / CC);
    float y = dv * rsqrtf(var + 1e-5f) * g2[tid] + b2[tid];
    g_attln[(size_t)head * NN * CC + r * CC + tid] = y;
}

// ---------------- kernel 6: out = 0.5*(elu(a0@W1_0^T)+elu(a1@W1_1^T)) ----------
__global__ __launch_bounds__(256) void k_ff1(const float* __restrict__ ff1_w,
                                             float* __restrict__ out) {
    __shared__ GemmSmem sm;
    int tid = threadIdx.x;
    int rowBase = blockIdx.x * 64;
    int ty = tid >> 4, tx = tid & 15;
    float res[4][8];
#pragma unroll 1
    for (int head = 0; head < KH; head++) {
        const float* W = ff1_w + head * CC * CC;
        const float* in = g_attln + (size_t)head * NN * CC;
        float acc[4][8] = {};
#pragma unroll 1
        for (int kBase = 0; kBase < CC; kBase += KCH)
            gemm_chunk(in, rowBase, W, kBase, sm, tid, ty, tx, acc);
#pragma unroll
        for (int i = 0; i < 4; i++)
#pragma unroll
            for (int q = 0; q < 8; q++) {
                float v = acc[i][q];
                float e = v > 0.f ? v : (expf(v) - 1.0f);   // elu, alpha=1
                if (head == 0) res[i][q] = e;
                else res[i][q] += e;
            }
    }
#pragma unroll
    for (int i = 0; i < 4; i++) {
        float4* p = (float4*)(out + (size_t)(rowBase + ty * 4 + i) * CC + tx * 8);
        p[0] = make_float4(res[i][0] * 0.5f, res[i][1] * 0.5f, res[i][2] * 0.5f, res[i][3] * 0.5f);
        p[1] = make_float4(res[i][4] * 0.5f, res[i][5] * 0.5f, res[i][6] * 0.5f, res[i][7] * 0.5f);
    }
}

// ---------------- launch (kernel launches ONLY — graph-capture safe) ----------
extern "C" void kernel_launch(void* const* d_in, const int* in_sizes, int n_in,
                              void* d_out, int out_size) {
    const float* x      = (const float*)d_in[0];
    const float* adj    = (const float*)d_in[1];
    const float* ff0_w  = (const float*)d_in[2];
    const float* ff1_w  = (const float*)d_in[3];
    const float* attn_w = (const float*)d_in[4];
    const float* g1     = (const float*)d_in[5];
    const float* b1     = (const float*)d_in[6];
    const float* g2     = (const float*)d_in[7];
    const float* b2     = (const float*)d_in[8];
    float* out = (float*)d_out;

    k_csr<<<NN / 8, 256>>>(adj);                       // 8 warps/block, warp per row
    k_ln<<<NN, 128>>>(x, g1, b1);
    k_gemm_h<<<dim3(NN / 64, KH), 256>>>(ff0_w);
    k_scores<<<dim3(NN, KH), 128>>>(attn_w);
    k_attn<<<dim3(NN, KH), 128>>>(x, g2, b2);
    k_ff1<<<NN / 64, 256>>>(ff1_w, out);
}

// round 5
// speedup vs baseline: 1.3401x; 1.3401x over previous
#include <cuda_runtime.h>
#include <math.h>

#define NN 6144
#define CC 128
#define KH 2
#define MAXD 192          // binomial(6143,0.01): mean deg 61, max row deg ~<110
#define TS 64             // GEMM row tile
#define PITCH 132         // smem row pitch (floats): 132*4B multiple of 16 -> float4 ok
#define KCH 16            // W chunk depth

// ---------------- scratch (__device__ globals; no allocation) ----------------
__device__ float g_h[KH * NN * CC];
__device__ float g_ssrc[KH * NN];
__device__ float g_sdst[KH * NN];
__device__ float g_attln[KH * NN * CC];
__device__ int   g_cols[NN * MAXD];
__device__ int   g_deg[NN];

// ---------------- reductions (128-thread blocks) ----------------
__device__ __forceinline__ float warpSum(float v) {
#pragma unroll
    for (int o = 16; o > 0; o >>= 1) v += __shfl_xor_sync(0xffffffffu, v, o);
    return v;
}
__device__ __forceinline__ float warpMax(float v) {
#pragma unroll
    for (int o = 16; o > 0; o >>= 1) v = fmaxf(v, __shfl_xor_sync(0xffffffffu, v, o));
    return v;
}
__device__ __forceinline__ float blockSum128(float v, float* red) {
    v = warpSum(v);
    if ((threadIdx.x & 31) == 0) red[threadIdx.x >> 5] = v;
    __syncthreads();
    float r = red[0] + red[1] + red[2] + red[3];
    __syncthreads();
    return r;
}
__device__ __forceinline__ float blockMax128(float v, float* red) {
    v = warpMax(v);
    if ((threadIdx.x & 31) == 0) red[threadIdx.x >> 5] = v;
    __syncthreads();
    float r = fmaxf(fmaxf(red[0], red[1]), fmaxf(red[2], red[3]));
    __syncthreads();
    return r;
}

// ---------------- kernel 1: ELL build from adj (warp per row) ----------------
__global__ __launch_bounds__(256) void k_csr(const float* __restrict__ adj) {
    int gw = (blockIdx.x * blockDim.x + threadIdx.x) >> 5;
    int lane = threadIdx.x & 31;
    if (gw >= NN) return;
    int row = gw;
    const float4* a4 = (const float4*)(adj + (size_t)row * NN);
    int* rcols = g_cols + (size_t)row * MAXD;
    int cnt = 0;
#pragma unroll 1
    for (int it = 0; it < NN / 128; it++) {
        int base = it * 128 + lane * 4;
        float4 v = a4[it * 32 + lane];
        unsigned m = 0;
        if (v.x > 0.f || base + 0 == row) m |= 1u;
        if (v.y > 0.f || base + 1 == row) m |= 2u;
        if (v.z > 0.f || base + 2 == row) m |= 4u;
        if (v.w > 0.f || base + 3 == row) m |= 8u;
        int c = __popc(m);
        int incl = c;
#pragma unroll
        for (int o = 1; o < 32; o <<= 1) {
            int t = __shfl_up_sync(0xffffffffu, incl, o);
            if (lane >= o) incl += t;
        }
        int total = __shfl_sync(0xffffffffu, incl, 31);
        int off = cnt + incl - c;      // exclusive offset for this thread
        if (m & 1u) { if (off < MAXD) rcols[off] = base + 0; off++; }
        if (m & 2u) { if (off < MAXD) rcols[off] = base + 1; off++; }
        if (m & 4u) { if (off < MAXD) rcols[off] = base + 2; off++; }
        if (m & 8u) { if (off < MAXD) rcols[off] = base + 3; off++; }
        cnt += total;
    }
    if (lane == 0) g_deg[row] = cnt < MAXD ? cnt : MAXD;
}

// ---------------- shared GEMM smem (static, ~43.5 KB) ----------------
struct GemmSmem {
    float sIn[TS][PITCH];     // input tile (LN'd in place for gemm_h)
    float sW[KCH][PITCH];     // W chunk, sW[k][o]
    float aw[2 * CC];         // attn_w slices (gemm_h only)
};

// Load a 64xCC input tile (float4) into sIn.
__device__ __forceinline__ void load_tile(const float* __restrict__ in, int rowBase,
                                          GemmSmem& sm, int tid) {
    const float4* in4 = (const float4*)(in + (size_t)rowBase * CC);
#pragma unroll
    for (int i = tid; i < TS * (CC / 4); i += 256) {
        int rr = i >> 5, c4 = i & 31;
        float4 v = in4[rr * 32 + c4];
        float* p = &sm.sIn[rr][c4 * 4];
        p[0] = v.x; p[1] = v.y; p[2] = v.z; p[3] = v.w;
    }
}

// GEMM mainloop: acc += sIn @ W^T, W row-major [o][c], chunked by KCH.
__device__ __forceinline__ void gemm_main(const float* __restrict__ W, GemmSmem& sm,
                                          int tid, int ty, int tx, float acc[4][8]) {
#pragma unroll 1
    for (int kb = 0; kb < CC; kb += KCH) {
#pragma unroll
        for (int i = tid; i < CC * KCH; i += 256) {
            int o = i >> 4, kk = i & 15;
            sm.sW[kk][o] = W[(size_t)o * CC + kb + kk];
        }
        __syncthreads();
#pragma unroll
        for (int k = 0; k < KCH; k++) {
            float a0 = sm.sIn[ty * 4 + 0][kb + k];
            float a1 = sm.sIn[ty * 4 + 1][kb + k];
            float a2 = sm.sIn[ty * 4 + 2][kb + k];
            float a3 = sm.sIn[ty * 4 + 3][kb + k];
            float4 b0 = *(const float4*)&sm.sW[k][tx * 8];
            float4 b1 = *(const float4*)&sm.sW[k][tx * 8 + 4];
            float bb[8] = {b0.x, b0.y, b0.z, b0.w, b1.x, b1.y, b1.z, b1.w};
#pragma unroll
            for (int q = 0; q < 8; q++) {
                acc[0][q] = fmaf(a0, bb[q], acc[0][q]);
                acc[1][q] = fmaf(a1, bb[q], acc[1][q]);
                acc[2][q] = fmaf(a2, bb[q], acc[2][q]);
                acc[3][q] = fmaf(a3, bb[q], acc[3][q]);
            }
        }
        __syncthreads();
    }
}

// ---------- kernel 2: fused LN + h-GEMM + attention scores   grid (NN/TS, KH) ----------
__global__ __launch_bounds__(256) void k_gemm_h(const float* __restrict__ x,
                                                const float* __restrict__ ff0_w,
                                                const float* __restrict__ attn_w,
                                                const float* __restrict__ g1,
                                                const float* __restrict__ b1) {
    __shared__ GemmSmem sm;
    int tid = threadIdx.x;
    int head = blockIdx.y;
    int rowBase = blockIdx.x * TS;

    load_tile(x, rowBase, sm, tid);
    if (tid < 2 * CC) sm.aw[tid] = attn_w[head * 2 * CC + tid];
    __syncthreads();

    // LayerNorm in smem: 4 lanes per row, lane l owns elems {l, l+4, l+8, ...} (bank-clean)
    {
        int rr = tid >> 2, l = tid & 3;
        float s = 0.f;
#pragma unroll
        for (int j = 0; j < 32; j++) s += sm.sIn[rr][l + 4 * j];
        s += __shfl_xor_sync(0xffffffffu, s, 1);
        s += __shfl_xor_sync(0xffffffffu, s, 2);
        float mean = s * (1.0f / CC);
        float vv = 0.f;
#pragma unroll
        for (int j = 0; j < 32; j++) { float d = sm.sIn[rr][l + 4 * j] - mean; vv += d * d; }
        vv += __shfl_xor_sync(0xffffffffu, vv, 1);
        vv += __shfl_xor_sync(0xffffffffu, vv, 2);
        float rs = rsqrtf(vv * (1.0f / CC) + 1e-5f);
#pragma unroll
        for (int j = 0; j < 32; j++) {
            int k = l + 4 * j;
            sm.sIn[rr][k] = (sm.sIn[rr][k] - mean) * rs * g1[k] + b1[k];
        }
    }
    __syncthreads();

    int ty = tid >> 4, tx = tid & 15;
    float acc[4][8] = {};
    gemm_main(ff0_w + (size_t)head * CC * CC, sm, tid, ty, tx, acc);

    // store h + fused scores epilogue
    float* out = g_h + (size_t)head * NN * CC;
    float p1[4] = {}, p2[4] = {};
#pragma unroll
    for (int i = 0; i < 4; i++) {
        float4* p = (float4*)(out + (size_t)(rowBase + ty * 4 + i) * CC + tx * 8);
        p[0] = make_float4(acc[i][0], acc[i][1], acc[i][2], acc[i][3]);
        p[1] = make_float4(acc[i][4], acc[i][5], acc[i][6], acc[i][7]);
#pragma unroll
        for (int q = 0; q < 8; q++) {
            p1[i] = fmaf(acc[i][q], sm.aw[tx * 8 + q], p1[i]);
            p2[i] = fmaf(acc[i][q], sm.aw[CC + tx * 8 + q], p2[i]);
        }
    }
    // reduce across the 16 tx lanes (xor <= 8 stays within each 16-lane half-warp)
#pragma unroll
    for (int i = 0; i < 4; i++) {
#pragma unroll
        for (int o = 1; o < 16; o <<= 1) {
            p1[i] += __shfl_xor_sync(0xffffffffu, p1[i], o);
            p2[i] += __shfl_xor_sync(0xffffffffu, p2[i], o);
        }
    }
    if (tx == 0) {
#pragma unroll
        for (int i = 0; i < 4; i++) {
            g_ssrc[head * NN + rowBase + ty * 4 + i] = p1[i];
            g_sdst[head * NN + rowBase + ty * 4 + i] = p2[i];
        }
    }
}

// ---------------- kernel 3: sparse softmax + PV + residual + LN ----------------
__global__ __launch_bounds__(128) void k_attn(const float* __restrict__ x,
                                              const float* __restrict__ g2,
                                              const float* __restrict__ b2) { // grid (NN, KH)
    __shared__ float ev[MAXD];
    __shared__ int cl[MAXD];
    __shared__ float red[4];
    int r = blockIdx.x, head = blockIdx.y, tid = threadIdx.x;
    int d = g_deg[r];
    float srow = g_ssrc[head * NN + r];
    const int* rcols = g_cols + (size_t)r * MAXD;

    float lmax = -1e30f;
    for (int j = tid; j < d; j += 128) {
        int c = rcols[j];
        float e = srow + g_sdst[head * NN + c];
        e = e > 0.f ? e : 0.01f * e;      // leaky_relu, slope 0.01
        ev[j] = e;
        cl[j] = c;
        lmax = fmaxf(lmax, e);
    }
    float m = blockMax128(lmax, red);
    float lsum = 0.f;
    for (int j = tid; j < d; j += 128) {
        float p = expf(ev[j] - m);
        ev[j] = p;
        lsum += p;
    }
    float Z = blockSum128(lsum, red);     // syncs inside make ev/cl visible

    const float* hh = g_h + (size_t)head * NN * CC;
    float acc = 0.f;
    int j = 0;
    for (; j + 4 <= d; j += 4) {          // MLP=4 on the L2-resident h gathers
        float p0 = ev[j + 0], p1 = ev[j + 1], p2 = ev[j + 2], p3 = ev[j + 3];
        const float* r0 = hh + (size_t)cl[j + 0] * CC;
        const float* r1 = hh + (size_t)cl[j + 1] * CC;
        const float* r2 = hh + (size_t)cl[j + 2] * CC;
        const float* r3 = hh + (size_t)cl[j + 3] * CC;
        float v0 = r0[tid], v1 = r1[tid], v2 = r2[tid], v3 = r3[tid];
        acc = fmaf(p0, v0, acc);
        acc = fmaf(p1, v1, acc);
        acc = fmaf(p2, v2, acc);
        acc = fmaf(p3, v3, acc);
    }
    for (; j < d; j++) acc = fmaf(ev[j], hh[(size_t)cl[j] * CC + tid], acc);

    float att = acc / Z + x[r * CC + tid];     // residual with pre-norm x
    float mean = blockSum128(att, red) * (1.0f / CC);
    float dv = att - mean;
    float var = blockSum128(dv * dv, red) * (1.0f / CC);
    float y = dv * rsqrtf(var + 1e-5f) * g2[tid] + b2[tid];
    g_attln[(size_t)head * NN * CC + r * CC + tid] = y;
}

// ---------------- kernel 4: out = 0.5*(elu(a0@W1_0^T)+elu(a1@W1_1^T)) ----------
__global__ __launch_bounds__(256) void k_ff1(const float* __restrict__ ff1_w,
                                             float* __restrict__ out) {
    __shared__ GemmSmem sm;
    int tid = threadIdx.x;
    int rowBase = blockIdx.x * TS;
    int ty = tid >> 4, tx = tid & 15;
    float res[4][8];
#pragma unroll 1
    for (int head = 0; head < KH; head++) {
        load_tile(g_attln + (size_t)head * NN * CC, rowBase, sm, tid);
        __syncthreads();
        float acc[4][8] = {};
        gemm_main(ff1_w + (size_t)head * CC * CC, sm, tid, ty, tx, acc);
#pragma unroll
        for (int i = 0; i < 4; i++)
#pragma unroll
            for (int q = 0; q < 8; q++) {
                float v = acc[i][q];
                float e = v > 0.f ? v : (expf(v) - 1.0f);   // elu, alpha=1
                if (head == 0) res[i][q] = e;
                else res[i][q] += e;
            }
        __syncthreads();   // compute done before next head's tile overwrites sIn
    }
#pragma unroll
    for (int i = 0; i < 4; i++) {
        float4* p = (float4*)(out + (size_t)(rowBase + ty * 4 + i) * CC + tx * 8);
        p[0] = make_float4(res[i][0] * 0.5f, res[i][1] * 0.5f, res[i][2] * 0.5f, res[i][3] * 0.5f);
        p[1] = make_float4(res[i][4] * 0.5f, res[i][5] * 0.5f, res[i][6] * 0.5f, res[i][7] * 0.5f);
    }
}

// ---------------- launch (kernel launches ONLY — graph-capture safe) ----------
extern "C" void kernel_launch(void* const* d_in, const int* in_sizes, int n_in,
                              void* d_out, int out_size) {
    const float* x      = (const float*)d_in[0];
    const float* adj    = (const float*)d_in[1];
    const float* ff0_w  = (const float*)d_in[2];
    const float* ff1_w  = (const float*)d_in[3];
    const float* attn_w = (const float*)d_in[4];
    const float* g1     = (const float*)d_in[5];
    const float* b1     = (const float*)d_in[6];
    const float* g2     = (const float*)d_in[7];
    const float* b2     = (const float*)d_in[8];
    float* out = (float*)d_out;

    k_csr<<<NN / 8, 256>>>(adj);                          // warp per row
    k_gemm_h<<<dim3(NN / TS, KH), 256>>>(x, ff0_w, attn_w, g1, b1);
    k_attn<<<dim3(NN, KH), 128>>>(x, g2, b2);
    k_ff1<<<NN / TS, 256>>>(ff1_w, out);
}